// round 3
// baseline (speedup 1.0000x reference)
#include <cuda_runtime.h>
#include <cstdint>
#include <cstddef>

#define N_ATOMS 262144
#define BATCH   4096
#define HIDDEN  256
#define SCALE   0.125f
#define LN_EPS  1e-5f
#define SM_EPS  1e-16f

// ---------------- scratch (device globals, no allocation) ----------------
__device__ float    g_A[HIDDEN * HIDDEN];   // A = Wq @ Wk^T   (A[k][h])
__device__ float    g_dvec[HIDDEN];         // d[h] = sum_j Wk[h,j]*bq[j]
__device__ float    g_vq[HIDDEN];           // vq[k] = sum_j Wq[k,j]*bk[j]
__device__ float    g_cconst[1];            // bq . bk
__device__ float    g_U[BATCH * HIDDEN];    // U[b][h] = p_b @ A + d
__device__ float    g_c[BATCH];             // c_b
__device__ float    g_e[N_ATOMS];           // dots, then exp(dots-m)
__device__ unsigned g_segmax[BATCH];        // ordered-key float max
__device__ float    g_segsum[BATCH];

// ---------------- K0: zero segment reducers every launch ----------------
__global__ void k_init() {
    int i = blockIdx.x * blockDim.x + threadIdx.x;
    if (i < BATCH) { g_segmax[i] = 0u; g_segsum[i] = 0.f; }
}

// ---------------- K1: A = Wq @ Wk^T, vq, dvec, cconst ----------------
__global__ void k_pre(const float* __restrict__ Wq, const float* __restrict__ bq,
                      const float* __restrict__ Wk, const float* __restrict__ bk) {
    int t = threadIdx.x;
    if (blockIdx.x < 32) {
        __shared__ float wq[8][HIDDEN];
        int k0 = blockIdx.x * 8;
        #pragma unroll
        for (int e = 0; e < 8; e++) wq[e][t] = Wq[(k0 + e) * HIDDEN + t];
        __syncthreads();
        float acc[8];
        #pragma unroll
        for (int r = 0; r < 8; r++) acc[r] = 0.f;
        for (int j = 0; j < HIDDEN; j++) {
            float w = __ldg(&Wk[t * HIDDEN + j]);
            #pragma unroll
            for (int r = 0; r < 8; r++) acc[r] += wq[r][j] * w;
        }
        #pragma unroll
        for (int r = 0; r < 8; r++) g_A[(k0 + r) * HIDDEN + t] = acc[r];
    } else {
        __shared__ float bqs[HIDDEN], bks[HIDDEN];
        bqs[t] = bq[t]; bks[t] = bk[t];
        __syncthreads();
        float v = 0.f, d = 0.f;
        for (int j = 0; j < HIDDEN; j++) {
            v += __ldg(&Wq[t * HIDDEN + j]) * bks[j];
            d += __ldg(&Wk[t * HIDDEN + j]) * bqs[j];
        }
        g_vq[t] = v; g_dvec[t] = d;
        if (t == 0) {
            float c = 0.f;
            for (int j = 0; j < HIDDEN; j++) c += bqs[j] * bks[j];
            g_cconst[0] = c;
        }
    }
}

// ---------------- K2: U = protein @ A + d ; c = protein @ vq + cc ----------------
__global__ void k_u(const float* __restrict__ P) {
    __shared__ float ps[HIDDEN][16];   // ps[k][r]
    __shared__ float vqs[HIDDEN];
    int t = threadIdx.x;
    int b0 = blockIdx.x * 16;
    #pragma unroll
    for (int e = 0; e < 16; e++) ps[t][e] = P[(b0 + e) * HIDDEN + t];
    vqs[t] = g_vq[t];
    __syncthreads();
    float acc[16];
    #pragma unroll
    for (int r = 0; r < 16; r++) acc[r] = 0.f;
    for (int k = 0; k < HIDDEN; k++) {
        float a = g_A[k * HIDDEN + t];
        const float4* p4 = (const float4*)ps[k];
        float4 x0 = p4[0], x1 = p4[1], x2 = p4[2], x3 = p4[3];
        acc[0]  += x0.x * a; acc[1]  += x0.y * a; acc[2]  += x0.z * a; acc[3]  += x0.w * a;
        acc[4]  += x1.x * a; acc[5]  += x1.y * a; acc[6]  += x1.z * a; acc[7]  += x1.w * a;
        acc[8]  += x2.x * a; acc[9]  += x2.y * a; acc[10] += x2.z * a; acc[11] += x2.w * a;
        acc[12] += x3.x * a; acc[13] += x3.y * a; acc[14] += x3.z * a; acc[15] += x3.w * a;
    }
    float dv = g_dvec[t];
    #pragma unroll
    for (int r = 0; r < 16; r++) g_U[(b0 + r) * HIDDEN + t] = acc[r] + dv;
    if (t < 16) {
        float s = 0.f;
        for (int k = 0; k < HIDDEN; k++) s += ps[k][t] * vqs[k];
        g_c[b0 + t] = s + g_cconst[0];
    }
}

// ---------------- K3: dots + segment max (one warp per atom) ----------------
__device__ __forceinline__ unsigned f_key(float f) {
    unsigned b = __float_as_uint(f);
    return (b & 0x80000000u) ? ~b : (b | 0x80000000u);
}
__device__ __forceinline__ float key_f(unsigned k) {
    return (k & 0x80000000u) ? __uint_as_float(k ^ 0x80000000u) : __uint_as_float(~k);
}

__global__ void k_dots(const float* __restrict__ drug, const int* __restrict__ bidx) {
    int warp = threadIdx.x >> 5, lane = threadIdx.x & 31;
    int i = blockIdx.x * 8 + warp;
    int b = bidx[i];
    const float4* dr = (const float4*)(drug + (size_t)i * HIDDEN);
    const float4* ur = (const float4*)(g_U + (size_t)b * HIDDEN);
    float4 d0 = dr[lane * 2], d1 = dr[lane * 2 + 1];
    float4 u0 = ur[lane * 2], u1 = ur[lane * 2 + 1];
    float s = d0.x * u0.x + d0.y * u0.y + d0.z * u0.z + d0.w * u0.w
            + d1.x * u1.x + d1.y * u1.y + d1.z * u1.z + d1.w * u1.w;
    #pragma unroll
    for (int off = 16; off > 0; off >>= 1) s += __shfl_xor_sync(0xFFFFFFFFu, s, off);
    if (lane == 0) {
        float val = (s + g_c[b]) * SCALE;
        g_e[i] = val;
        atomicMax(&g_segmax[b], f_key(val));
    }
}

// ---------------- K4: e = exp(dots - m), segment sum ----------------
__global__ void k_exp(const int* __restrict__ bidx) {
    int i = blockIdx.x * blockDim.x + threadIdx.x;
    int b = bidx[i];
    float m = key_f(g_segmax[b]);
    float e = expf(g_e[i] - m);
    g_e[i] = e;
    atomicAdd(&g_segsum[b], e);
}

// ---------------- K5: V GEMM (tf32 mma) + attn*V + residual + LayerNorm ----------------
#define BM 128
#define BK 32

struct alignas(16) Smem5 {
    float drug[BM][260];       // stride 260: conflict-free A-frag loads
    float wv[2][BK][264];      // stride 264: conflict-free B-frag loads
    float attn[BM];
    float bvs[HIDDEN];
    float gms[HIDDEN];
    float bts[HIDDEN];
    float rs[4][BM];
    float rq[4][BM];
};

__device__ __forceinline__ void cp16(void* s, const void* g) {
    unsigned sa = (unsigned)__cvta_generic_to_shared(s);
    asm volatile("cp.async.cg.shared.global [%0], [%1], 16;" :: "r"(sa), "l"(g));
}
__device__ __forceinline__ unsigned f2tf(float f) {
    unsigned r; asm("cvt.rna.tf32.f32 %0, %1;" : "=r"(r) : "f"(f)); return r;
}
__device__ __forceinline__ void mma8(float* c, const unsigned* a, const unsigned* b) {
    asm volatile(
        "mma.sync.aligned.m16n8k8.row.col.f32.tf32.tf32.f32 "
        "{%0,%1,%2,%3}, {%4,%5,%6,%7}, {%8,%9}, {%0,%1,%2,%3};"
        : "+f"(c[0]), "+f"(c[1]), "+f"(c[2]), "+f"(c[3])
        : "r"(a[0]), "r"(a[1]), "r"(a[2]), "r"(a[3]), "r"(b[0]), "r"(b[1]));
}

__global__ void __launch_bounds__(512, 1) k_main(
    const float* __restrict__ drug, const int* __restrict__ bidx,
    const float* __restrict__ Wv, const float* __restrict__ bv,
    const float* __restrict__ gamma, const float* __restrict__ beta,
    float* __restrict__ out, float* __restrict__ attn_out)
{
    extern __shared__ char smem_raw[];
    Smem5& sm = *(Smem5*)smem_raw;
    int t = threadIdx.x;
    int w = t >> 5, lane = t & 31;
    int g = lane >> 2, tig = lane & 3;
    int wm = w >> 2, wn = w & 3;          // 4x4 warp grid: M=32, N=64 per warp
    int rb = blockIdx.x * BM;

    // stage drug tile (full K=256 row — doubles as residual) + Wv stage 0
    #pragma unroll
    for (int e = 0; e < 16; e++) {
        int idx = e * 512 + t;             // 0..8191 float4s
        int row = idx >> 6, c4 = idx & 63;
        cp16(&sm.drug[row][c4 * 4], drug + (size_t)(rb + row) * HIDDEN + c4 * 4);
    }
    #pragma unroll
    for (int e = 0; e < 4; e++) {
        int idx = e * 512 + t;             // 0..2047
        int r = idx >> 6, c4 = idx & 63;
        cp16(&sm.wv[0][r][c4 * 4], Wv + (size_t)r * HIDDEN + c4 * 4);
    }
    asm volatile("cp.async.commit_group;");

    if (t < BM) {
        int i = rb + t;
        int b = bidx[i];
        float a = g_e[i] / (g_segsum[b] + SM_EPS);
        sm.attn[t] = a;
        if (attn_out) attn_out[i] = a;
    } else if (t < BM + HIDDEN) {
        int c = t - BM;
        sm.bvs[c] = bv[c]; sm.gms[c] = gamma[c]; sm.bts[c] = beta[c];
    }

    asm volatile("cp.async.wait_group 0;" ::: "memory");
    __syncthreads();

    float acc[2][8][4];
    #pragma unroll
    for (int mt = 0; mt < 2; mt++)
        #pragma unroll
        for (int nt = 0; nt < 8; nt++)
            #pragma unroll
            for (int q = 0; q < 4; q++) acc[mt][nt][q] = 0.f;

    for (int s = 0; s < 8; s++) {
        if (s < 7) {
            int ks = (s + 1) * BK;
            int nbuf = (s + 1) & 1;
            #pragma unroll
            for (int e = 0; e < 4; e++) {
                int idx = e * 512 + t;
                int r = idx >> 6, c4 = idx & 63;
                cp16(&sm.wv[nbuf][r][c4 * 4], Wv + (size_t)(ks + r) * HIDDEN + c4 * 4);
            }
            asm volatile("cp.async.commit_group;");
        }
        int buf = s & 1;
        #pragma unroll
        for (int k8 = 0; k8 < 4; k8++) {
            int kk = s * BK + k8 * 8;
            unsigned ua[2][4];
            #pragma unroll
            for (int mt = 0; mt < 2; mt++) {
                int r0 = wm * 32 + mt * 16 + g;
                ua[mt][0] = f2tf(sm.drug[r0][kk + tig]);
                ua[mt][1] = f2tf(sm.drug[r0 + 8][kk + tig]);
                ua[mt][2] = f2tf(sm.drug[r0][kk + tig + 4]);
                ua[mt][3] = f2tf(sm.drug[r0 + 8][kk + tig + 4]);
            }
            #pragma unroll
            for (int nt = 0; nt < 8; nt++) {
                int c0 = wn * 64 + nt * 8 + g;
                unsigned ub[2];
                ub[0] = f2tf(sm.wv[buf][k8 * 8 + tig][c0]);
                ub[1] = f2tf(sm.wv[buf][k8 * 8 + tig + 4][c0]);
                mma8(acc[0][nt], ua[0], ub);
                mma8(acc[1][nt], ua[1], ub);
            }
        }
        if (s < 7) asm volatile("cp.async.wait_group 0;" ::: "memory");
        __syncthreads();
    }

    // epilogue: v = attn*(acc+bv) + drug ; per-row LN stats across the 4 N-warps
    float rsum[2][2], rsq[2][2];
    #pragma unroll
    for (int mt = 0; mt < 2; mt++) { rsum[mt][0] = rsum[mt][1] = 0.f; rsq[mt][0] = rsq[mt][1] = 0.f; }

    #pragma unroll
    for (int mt = 0; mt < 2; mt++) {
        int r0 = wm * 32 + mt * 16 + g, r1 = r0 + 8;
        float a0 = sm.attn[r0], a1 = sm.attn[r1];
        #pragma unroll
        for (int nt = 0; nt < 8; nt++) {
            int c0 = wn * 64 + nt * 8 + 2 * tig;
            float bv0 = sm.bvs[c0], bv1 = sm.bvs[c0 + 1];
            float v0 = a0 * (acc[mt][nt][0] + bv0) + sm.drug[r0][c0];
            float v1 = a0 * (acc[mt][nt][1] + bv1) + sm.drug[r0][c0 + 1];
            float v2 = a1 * (acc[mt][nt][2] + bv0) + sm.drug[r1][c0];
            float v3 = a1 * (acc[mt][nt][3] + bv1) + sm.drug[r1][c0 + 1];
            acc[mt][nt][0] = v0; acc[mt][nt][1] = v1; acc[mt][nt][2] = v2; acc[mt][nt][3] = v3;
            rsum[mt][0] += v0 + v1;           rsq[mt][0] += v0 * v0 + v1 * v1;
            rsum[mt][1] += v2 + v3;           rsq[mt][1] += v2 * v2 + v3 * v3;
        }
    }
    #pragma unroll
    for (int off = 1; off <= 2; off <<= 1) {
        #pragma unroll
        for (int mt = 0; mt < 2; mt++)
            #pragma unroll
            for (int h = 0; h < 2; h++) {
                rsum[mt][h] += __shfl_xor_sync(0xFFFFFFFFu, rsum[mt][h], off);
                rsq[mt][h]  += __shfl_xor_sync(0xFFFFFFFFu, rsq[mt][h], off);
            }
    }
    if (tig == 0) {
        #pragma unroll
        for (int mt = 0; mt < 2; mt++)
            #pragma unroll
            for (int h = 0; h < 2; h++) {
                int row = wm * 32 + mt * 16 + h * 8 + g;
                sm.rs[wn][row] = rsum[mt][h];
                sm.rq[wn][row] = rsq[mt][h];
            }
    }
    __syncthreads();

    #pragma unroll
    for (int mt = 0; mt < 2; mt++) {
        #pragma unroll
        for (int h = 0; h < 2; h++) {
            int row = wm * 32 + mt * 16 + h * 8 + g;
            float ts = sm.rs[0][row] + sm.rs[1][row] + sm.rs[2][row] + sm.rs[3][row];
            float tq = sm.rq[0][row] + sm.rq[1][row] + sm.rq[2][row] + sm.rq[3][row];
            float mu = ts * (1.f / HIDDEN);
            float var = tq * (1.f / HIDDEN) - mu * mu;
            float rstd = rsqrtf(var + LN_EPS);
            #pragma unroll
            for (int nt = 0; nt < 8; nt++) {
                int c0 = wn * 64 + nt * 8 + 2 * tig;
                float v0 = acc[mt][nt][h * 2 + 0];
                float v1 = acc[mt][nt][h * 2 + 1];
                float y0 = (v0 - mu) * rstd * sm.gms[c0] + sm.bts[c0];
                float y1 = (v1 - mu) * rstd * sm.gms[c0 + 1] + sm.bts[c0 + 1];
                float2 y = make_float2(y0, y1);
                *(float2*)&out[(size_t)(rb + row) * HIDDEN + c0] = y;
            }
        }
    }
}

// ---------------- host ----------------
extern "C" void kernel_launch(void* const* d_in, const int* in_sizes, int n_in,
                              void* d_out, int out_size) {
    const float* drug  = (const float*)d_in[0];
    const float* prot  = (const float*)d_in[1];
    const int*   bidx  = (const int*)d_in[2];
    const float* Wq    = (const float*)d_in[3];
    const float* bq    = (const float*)d_in[4];
    const float* Wk    = (const float*)d_in[5];
    const float* bk    = (const float*)d_in[6];
    const float* Wv    = (const float*)d_in[7];
    const float* bv    = (const float*)d_in[8];
    const float* gamma = (const float*)d_in[9];
    const float* beta  = (const float*)d_in[10];

    float* out = (float*)d_out;
    float* attn_out = (out_size >= (int)((size_t)N_ATOMS * HIDDEN + N_ATOMS))
                        ? out + (size_t)N_ATOMS * HIDDEN : nullptr;

    cudaFuncSetAttribute(k_main, cudaFuncAttributeMaxDynamicSharedMemorySize,
                         (int)sizeof(Smem5));

    k_init<<<BATCH / 256, 256>>>();
    k_pre <<<33, 256>>>(Wq, bq, Wk, bk);
    k_u   <<<BATCH / 16, 256>>>(prot);
    k_dots<<<N_ATOMS / 8, 256>>>(drug, bidx);
    k_exp <<<N_ATOMS / 256, 256>>>(bidx);
    k_main<<<N_ATOMS / BM, 512, sizeof(Smem5)>>>(drug, bidx, Wv, bv, gamma, beta,
                                                 out, attn_out);
}

// round 5
// speedup vs baseline: 1.2870x; 1.2870x over previous
#include <cuda_runtime.h>
#include <cuda_fp16.h>
#include <cstdint>
#include <cstddef>

#define N_ATOMS 262144
#define BATCH   4096
#define HIDDEN  256
#define SCALE   0.125f
#define LN_EPS  1e-5f
#define SM_EPS  1e-16f

// ---------------- scratch (device globals, no allocation) ----------------
__device__ float    g_A[HIDDEN * HIDDEN];   // A = Wq @ Wk^T
__device__ float    g_dvec[HIDDEN];
__device__ float    g_vq[HIDDEN];
__device__ float    g_cconst[1];
__device__ float    g_U[BATCH * HIDDEN];
__device__ float    g_c[BATCH];
__device__ float    g_e[N_ATOMS];
__device__ unsigned g_segmax[BATCH];
__device__ float    g_segsum[BATCH];
__device__ __half   g_WvT16[HIDDEN * HIDDEN]; // WvT16[n][k] = fp16(Wv[k][n])

// ---------------- K0: zero segment reducers ----------------
__global__ void k_init() {
    int i = blockIdx.x * blockDim.x + threadIdx.x;
    if (i < BATCH) { g_segmax[i] = 0u; g_segsum[i] = 0.f; }
}

// ---------------- K1: A = Wq @ Wk^T, vq, dvec, cconst ----------------
__global__ void k_pre(const float* __restrict__ Wq, const float* __restrict__ bq,
                      const float* __restrict__ Wk, const float* __restrict__ bk) {
    int t = threadIdx.x;
    if (blockIdx.x < 32) {
        __shared__ float wq[8][HIDDEN];
        int k0 = blockIdx.x * 8;
        #pragma unroll
        for (int e = 0; e < 8; e++) wq[e][t] = Wq[(k0 + e) * HIDDEN + t];
        __syncthreads();
        float acc[8];
        #pragma unroll
        for (int r = 0; r < 8; r++) acc[r] = 0.f;
        for (int j = 0; j < HIDDEN; j++) {
            float w = __ldg(&Wk[t * HIDDEN + j]);
            #pragma unroll
            for (int r = 0; r < 8; r++) acc[r] += wq[r][j] * w;
        }
        #pragma unroll
        for (int r = 0; r < 8; r++) g_A[(k0 + r) * HIDDEN + t] = acc[r];
    } else {
        __shared__ float bqs[HIDDEN], bks[HIDDEN];
        bqs[t] = bq[t]; bks[t] = bk[t];
        __syncthreads();
        float v = 0.f, d = 0.f;
        for (int j = 0; j < HIDDEN; j++) {
            v += __ldg(&Wq[t * HIDDEN + j]) * bks[j];
            d += __ldg(&Wk[t * HIDDEN + j]) * bqs[j];
        }
        g_vq[t] = v; g_dvec[t] = d;
        if (t == 0) {
            float c = 0.f;
            for (int j = 0; j < HIDDEN; j++) c += bqs[j] * bks[j];
            g_cconst[0] = c;
        }
    }
}

// ---------------- K2: U = protein @ A + d ; c = protein @ vq + cc ----------------
__global__ void k_u(const float* __restrict__ P) {
    __shared__ float ps[HIDDEN][16];
    __shared__ float vqs[HIDDEN];
    int t = threadIdx.x;
    int b0 = blockIdx.x * 16;
    #pragma unroll
    for (int e = 0; e < 16; e++) ps[t][e] = P[(b0 + e) * HIDDEN + t];
    vqs[t] = g_vq[t];
    __syncthreads();
    float acc[16];
    #pragma unroll
    for (int r = 0; r < 16; r++) acc[r] = 0.f;
    for (int k = 0; k < HIDDEN; k++) {
        float a = g_A[k * HIDDEN + t];
        const float4* p4 = (const float4*)ps[k];
        float4 x0 = p4[0], x1 = p4[1], x2 = p4[2], x3 = p4[3];
        acc[0]  += x0.x * a; acc[1]  += x0.y * a; acc[2]  += x0.z * a; acc[3]  += x0.w * a;
        acc[4]  += x1.x * a; acc[5]  += x1.y * a; acc[6]  += x1.z * a; acc[7]  += x1.w * a;
        acc[8]  += x2.x * a; acc[9]  += x2.y * a; acc[10] += x2.z * a; acc[11] += x2.w * a;
        acc[12] += x3.x * a; acc[13] += x3.y * a; acc[14] += x3.z * a; acc[15] += x3.w * a;
    }
    float dv = g_dvec[t];
    #pragma unroll
    for (int r = 0; r < 16; r++) g_U[(b0 + r) * HIDDEN + t] = acc[r] + dv;
    if (t < 16) {
        float s = 0.f;
        for (int k = 0; k < HIDDEN; k++) s += ps[k][t] * vqs[k];
        g_c[b0 + t] = s + g_cconst[0];
    }
}

// ---------------- K2b: transpose Wv -> g_WvT16 (n-major, fp16) ----------------
__global__ void k_t(const float* __restrict__ Wv) {
    __shared__ float ts[32][33];
    int x = threadIdx.x, y = threadIdx.y;           // 32 x 8
    int bx = blockIdx.x * 32, by = blockIdx.y * 32;
    #pragma unroll
    for (int j = 0; j < 32; j += 8) ts[y + j][x] = Wv[(by + y + j) * HIDDEN + bx + x];
    __syncthreads();
    #pragma unroll
    for (int j = 0; j < 32; j += 8)
        g_WvT16[(bx + y + j) * HIDDEN + by + x] = __float2half_rn(ts[x][y + j]);
}

// ---------------- K3: dots + segment max (warp handles 2 atoms) ----------------
__device__ __forceinline__ unsigned f_key(float f) {
    unsigned b = __float_as_uint(f);
    return (b & 0x80000000u) ? ~b : (b | 0x80000000u);
}
__device__ __forceinline__ float key_f(unsigned k) {
    return (k & 0x80000000u) ? __uint_as_float(k ^ 0x80000000u) : __uint_as_float(~k);
}

__global__ void k_dots(const float* __restrict__ drug, const int* __restrict__ bidx) {
    int warp = threadIdx.x >> 5, lane = threadIdx.x & 31;
    int i0 = (blockIdx.x * 8 + warp) * 2;
    int b0 = bidx[i0], b1 = bidx[i0 + 1];
    const float4* d0 = (const float4*)(drug + (size_t)i0 * HIDDEN);
    const float4* d1 = (const float4*)(drug + (size_t)(i0 + 1) * HIDDEN);
    const float4* u0 = (const float4*)(g_U + (size_t)b0 * HIDDEN);
    const float4* u1 = (const float4*)(g_U + (size_t)b1 * HIDDEN);
    float4 x0 = d0[lane * 2], x1 = d0[lane * 2 + 1];
    float4 x2 = d1[lane * 2], x3 = d1[lane * 2 + 1];
    float4 y0 = u0[lane * 2], y1 = u0[lane * 2 + 1];
    float4 y2 = u1[lane * 2], y3 = u1[lane * 2 + 1];
    float s0 = x0.x * y0.x + x0.y * y0.y + x0.z * y0.z + x0.w * y0.w
             + x1.x * y1.x + x1.y * y1.y + x1.z * y1.z + x1.w * y1.w;
    float s1 = x2.x * y2.x + x2.y * y2.y + x2.z * y2.z + x2.w * y2.w
             + x3.x * y3.x + x3.y * y3.y + x3.z * y3.z + x3.w * y3.w;
    #pragma unroll
    for (int off = 16; off > 0; off >>= 1) {
        s0 += __shfl_xor_sync(0xFFFFFFFFu, s0, off);
        s1 += __shfl_xor_sync(0xFFFFFFFFu, s1, off);
    }
    if (lane == 0) {
        float v0 = (s0 + g_c[b0]) * SCALE;
        float v1 = (s1 + g_c[b1]) * SCALE;
        g_e[i0]     = v0;
        g_e[i0 + 1] = v1;
        atomicMax(&g_segmax[b0], f_key(v0));
        atomicMax(&g_segmax[b1], f_key(v1));
    }
}

// ---------------- K4: e = exp(dots - m), segment sum ----------------
__global__ void k_exp(const int* __restrict__ bidx) {
    int i = blockIdx.x * blockDim.x + threadIdx.x;
    int b = bidx[i];
    float m = key_f(g_segmax[b]);
    float e = expf(g_e[i] - m);
    g_e[i] = e;
    atomicAdd(&g_segsum[b], e);
}

// ---------------- K5: fp16 legacy-mma V-GEMM + attn*V + residual + LayerNorm ----
// M=128 x N=256 x K=256 per CTA; fp16 m16n8k16, both operands via ldmatrix.
// A tile: fp32 drug -> fp16 in smem (pitch 264 halves, 132 banks == 4 mod 32:
// conflict-free ldmatrix). B: WvT fp16, k=64 double-buffered chunks (pitch 72).
// Residual re-read as fp32 from gmem in the epilogue (L2-hot, 32B sectors).

#define APITCH 264
#define BPITCH 72

struct alignas(16) Sm {
    __half a[128 * APITCH];            // 67,584 B
    __half b[2][256 * BPITCH];         // 73,728 B
    float  attn[128];
    float  bvv[HIDDEN], gm[HIDDEN], bt[HIDDEN];
    float  rs[4][128], rq[4][128];
};

__device__ __forceinline__ void cp16(void* s, const void* g) {
    unsigned sa = (unsigned)__cvta_generic_to_shared(s);
    asm volatile("cp.async.cg.shared.global [%0], [%1], 16;" :: "r"(sa), "l"(g));
}
__device__ __forceinline__ void ldsm4(unsigned* r, unsigned addr) {
    asm volatile("ldmatrix.sync.aligned.m8n8.x4.shared.b16 {%0,%1,%2,%3}, [%4];"
        : "=r"(r[0]), "=r"(r[1]), "=r"(r[2]), "=r"(r[3]) : "r"(addr));
}
__device__ __forceinline__ void mma16(float* c, const unsigned* a, const unsigned* b) {
    asm volatile(
        "mma.sync.aligned.m16n8k16.row.col.f32.f16.f16.f32 "
        "{%0,%1,%2,%3},{%4,%5,%6,%7},{%8,%9},{%0,%1,%2,%3};"
        : "+f"(c[0]), "+f"(c[1]), "+f"(c[2]), "+f"(c[3])
        : "r"(a[0]), "r"(a[1]), "r"(a[2]), "r"(a[3]), "r"(b[0]), "r"(b[1]));
}

__global__ void __launch_bounds__(512, 1) k_main(
    const float* __restrict__ drug, const int* __restrict__ bidx,
    const float* __restrict__ bv, const float* __restrict__ gamma,
    const float* __restrict__ beta,
    float* __restrict__ out, float* __restrict__ attn_out)
{
    extern __shared__ char smem_raw[];
    Sm& sm = *(Sm*)smem_raw;
    int t = threadIdx.x;
    int w = t >> 5, lane = t & 31;
    int g = lane >> 2, tig = lane & 3;
    int wm = w >> 2, wn = w & 3;          // 4x4 warps: 32 rows x 64 cols each
    int rb = blockIdx.x * 128;

    // B chunk 0 (k cols 0..63) via cp.async
    #pragma unroll
    for (int e = 0; e < 4; e++) {
        int idx = e * 512 + t;             // 2048 16B pieces
        int n = idx >> 3, j = idx & 7;
        cp16(&sm.b[0][n * BPITCH + j * 8], g_WvT16 + n * HIDDEN + j * 8);
    }
    asm volatile("cp.async.commit_group;");

    // A: fp32 drug -> fp16 smem tile
    #pragma unroll
    for (int e = 0; e < 16; e++) {
        int idx = e * 512 + t;             // 8192 float4s
        int row = idx >> 6, c4 = idx & 63;
        float4 v = __ldg((const float4*)(drug + (size_t)(rb + row) * HIDDEN + c4 * 4));
        __half2 h0 = __float22half2_rn(make_float2(v.x, v.y));
        __half2 h1 = __float22half2_rn(make_float2(v.z, v.w));
        uint2 pk = make_uint2(*(unsigned*)&h0, *(unsigned*)&h1);
        *(uint2*)&sm.a[row * APITCH + c4 * 4] = pk;
    }

    if (t < 128) {
        int i = rb + t;
        int b = bidx[i];
        float a = g_e[i] / (g_segsum[b] + SM_EPS);
        sm.attn[t] = a;
        if (attn_out) attn_out[i] = a;
    } else if (t < 384) {
        int c = t - 128;
        sm.bvv[c] = bv[c]; sm.gm[c] = gamma[c]; sm.bt[c] = beta[c];
    }

    asm volatile("cp.async.wait_group 0;" ::: "memory");
    __syncthreads();

    float acc[2][8][4];
    #pragma unroll
    for (int mt = 0; mt < 2; mt++)
        #pragma unroll
        for (int nt = 0; nt < 8; nt++)
            #pragma unroll
            for (int q = 0; q < 4; q++) acc[mt][nt][q] = 0.f;

    unsigned aBase = (unsigned)__cvta_generic_to_shared(sm.a);
    unsigned bBase0 = (unsigned)__cvta_generic_to_shared(sm.b[0]);
    unsigned bBase1 = (unsigned)__cvta_generic_to_shared(sm.b[1]);

    // precompute lane-dependent address parts
    unsigned aLane0 = aBase + (unsigned)((wm * 32 + (lane & 15)) * APITCH * 2
                                         + ((lane >> 4) << 3) * 2);
    unsigned bLaneRow = (unsigned)((wn * 64 + ((lane >> 4) << 3) + (lane & 7)) * BPITCH * 2);
    unsigned bLaneK   = (unsigned)((((lane >> 3) & 1) << 3) * 2);

    for (int c = 0; c < 4; c++) {
        if (c < 3) {
            #pragma unroll
            for (int e = 0; e < 4; e++) {
                int idx = e * 512 + t;
                int n = idx >> 3, j = idx & 7;
                cp16(&sm.b[(c + 1) & 1][n * BPITCH + j * 8],
                     g_WvT16 + n * HIDDEN + (c + 1) * 64 + j * 8);
            }
            asm volatile("cp.async.commit_group;");
        }
        unsigned bB = (c & 1) ? bBase1 : bBase0;
        #pragma unroll
        for (int k16 = 0; k16 < 4; k16++) {
            int kA = c * 64 + k16 * 16;
            unsigned a0[4], a1[4];
            ldsm4(a0, aLane0 + (unsigned)(kA * 2));
            ldsm4(a1, aLane0 + (unsigned)(16 * APITCH * 2 + kA * 2));
            #pragma unroll
            for (int p = 0; p < 4; p++) {
                unsigned bq[4];
                unsigned baddr = bB + bLaneRow + (unsigned)(p * 16 * BPITCH * 2)
                               + (unsigned)(k16 * 16 * 2) + bLaneK;
                ldsm4(bq, baddr);
                mma16(acc[0][2 * p],     a0, &bq[0]);
                mma16(acc[1][2 * p],     a1, &bq[0]);
                mma16(acc[0][2 * p + 1], a0, &bq[2]);
                mma16(acc[1][2 * p + 1], a1, &bq[2]);
            }
        }
        if (c < 3) asm volatile("cp.async.wait_group 0;" ::: "memory");
        __syncthreads();
    }

    // epilogue: v = attn*(acc+bv) + drug(fp32 from gmem) ; LN across 4 N-warps
    float rsum[2][2], rsq[2][2];
    #pragma unroll
    for (int mt = 0; mt < 2; mt++) { rsum[mt][0] = rsum[mt][1] = 0.f; rsq[mt][0] = rsq[mt][1] = 0.f; }

    #pragma unroll
    for (int mt = 0; mt < 2; mt++) {
        int r0 = wm * 32 + mt * 16 + g, r1 = r0 + 8;
        float a0 = sm.attn[r0], a1 = sm.attn[r1];
        const float* drow0 = drug + (size_t)(rb + r0) * HIDDEN;
        const float* drow1 = drug + (size_t)(rb + r1) * HIDDEN;
        #pragma unroll
        for (int nt = 0; nt < 8; nt++) {
            int c0 = wn * 64 + nt * 8 + 2 * tig;
            float2 q0 = __ldg((const float2*)(drow0 + c0));
            float2 q1 = __ldg((const float2*)(drow1 + c0));
            float bv0 = sm.bvv[c0], bv1 = sm.bvv[c0 + 1];
            float v0 = fmaf(a0, acc[mt][nt][0] + bv0, q0.x);
            float v1 = fmaf(a0, acc[mt][nt][1] + bv1, q0.y);
            float v2 = fmaf(a1, acc[mt][nt][2] + bv0, q1.x);
            float v3 = fmaf(a1, acc[mt][nt][3] + bv1, q1.y);
            acc[mt][nt][0] = v0; acc[mt][nt][1] = v1; acc[mt][nt][2] = v2; acc[mt][nt][3] = v3;
            rsum[mt][0] += v0 + v1;           rsq[mt][0] += v0 * v0 + v1 * v1;
            rsum[mt][1] += v2 + v3;           rsq[mt][1] += v2 * v2 + v3 * v3;
        }
    }
    #pragma unroll
    for (int off = 1; off <= 2; off <<= 1) {
        #pragma unroll
        for (int mt = 0; mt < 2; mt++)
            #pragma unroll
            for (int h = 0; h < 2; h++) {
                rsum[mt][h] += __shfl_xor_sync(0xFFFFFFFFu, rsum[mt][h], off);
                rsq[mt][h]  += __shfl_xor_sync(0xFFFFFFFFu, rsq[mt][h], off);
            }
    }
    if (tig == 0) {
        #pragma unroll
        for (int mt = 0; mt < 2; mt++)
            #pragma unroll
            for (int h = 0; h < 2; h++) {
                int row = wm * 32 + mt * 16 + h * 8 + g;
                sm.rs[wn][row] = rsum[mt][h];
                sm.rq[wn][row] = rsq[mt][h];
            }
    }
    __syncthreads();

    #pragma unroll
    for (int mt = 0; mt < 2; mt++) {
        #pragma unroll
        for (int h = 0; h < 2; h++) {
            int row = wm * 32 + mt * 16 + h * 8 + g;
            float ts = sm.rs[0][row] + sm.rs[1][row] + sm.rs[2][row] + sm.rs[3][row];
            float tq = sm.rq[0][row] + sm.rq[1][row] + sm.rq[2][row] + sm.rq[3][row];
            float mu = ts * (1.f / HIDDEN);
            float var = tq * (1.f / HIDDEN) - mu * mu;
            float rstd = rsqrtf(var + LN_EPS);
            #pragma unroll
            for (int nt = 0; nt < 8; nt++) {
                int c0 = wn * 64 + nt * 8 + 2 * tig;
                float v0 = acc[mt][nt][h * 2 + 0];
                float v1 = acc[mt][nt][h * 2 + 1];
                float y0 = fmaf((v0 - mu) * rstd, sm.gm[c0],     sm.bt[c0]);
                float y1 = fmaf((v1 - mu) * rstd, sm.gm[c0 + 1], sm.bt[c0 + 1]);
                *(float2*)&out[(size_t)(rb + row) * HIDDEN + c0] = make_float2(y0, y1);
            }
        }
    }
}

// ---------------- host ----------------
extern "C" void kernel_launch(void* const* d_in, const int* in_sizes, int n_in,
                              void* d_out, int out_size) {
    const float* drug  = (const float*)d_in[0];
    const float* prot  = (const float*)d_in[1];
    const int*   bidx  = (const int*)d_in[2];
    const float* Wq    = (const float*)d_in[3];
    const float* bq    = (const float*)d_in[4];
    const float* Wk    = (const float*)d_in[5];
    const float* bk    = (const float*)d_in[6];
    const float* Wv    = (const float*)d_in[7];
    const float* bv    = (const float*)d_in[8];
    const float* gamma = (const float*)d_in[9];
    const float* beta  = (const float*)d_in[10];

    float* out = (float*)d_out;
    float* attn_out = (out_size >= (int)((size_t)N_ATOMS * HIDDEN + N_ATOMS))
                        ? out + (size_t)N_ATOMS * HIDDEN : nullptr;

    cudaFuncSetAttribute(k_main, cudaFuncAttributeMaxDynamicSharedMemorySize,
                         (int)sizeof(Sm));

    k_init<<<BATCH / 256, 256>>>();
    k_pre <<<33, 256>>>(Wq, bq, Wk, bk);
    k_u   <<<BATCH / 16, 256>>>(prot);
    k_t   <<<dim3(8, 8), dim3(32, 8)>>>(Wv);
    k_dots<<<N_ATOMS / 16, 256>>>(drug, bidx);
    k_exp <<<N_ATOMS / 256, 256>>>(bidx);
    k_main<<<N_ATOMS / 128, 512, sizeof(Sm)>>>(drug, bidx, bv, gamma, beta,
                                               out, attn_out);
}